// round 14
// baseline (speedup 1.0000x reference)
#include <cuda_runtime.h>
#include <cuda_fp16.h>
#include <cstdint>
#include <cstddef>

#define NN 50000
#define EE 800000
#define ET (EE + NN)

// ---------------- scratch (device globals; no allocation allowed) ----------
__device__ __align__(16) __half g_xp1h[(size_t)NN * 256];
__device__ __align__(16) __half g_xp2h[(size_t)NN * 64];
__device__ __align__(16) float  g_skip[(size_t)NN * 64];
__device__ __align__(16) __half g_xa16[(size_t)NN * 256];
__device__ __align__(16) __half g_xc16[(size_t)NN * 256];
__device__ __align__(16) __half g_h16[(size_t)NN * 256];
__device__ __align__(16) __half g_hs16[(size_t)NN * 256];
__device__ __align__(16) __half g_w1t16[384 * 256];        // W1^T fp16 + 8 aug rows (padded)
__device__ __align__(16) __half g_w2t16[128 * 256];        // W2^T fp16 + 2 aug rows (padded)
__device__ __align__(16) float g_als1[(size_t)NN * 4];
__device__ __align__(16) float g_ald1[(size_t)NN * 4];
__device__ __align__(16) float g_als2[NN];
__device__ __align__(16) float g_ald2[NN];
__device__ int g_deg[NN];
__device__ int g_offs[NN + 1];
__device__ int g_cur[NN];
__device__ int g_ssrc[ET];
__device__ int g_bsum[256];
__device__ int g_bpre[256];

// ------- prep A: xa16 + weight tables + aug logit columns -------------------
__global__ void cvt_a_kernel(const float* __restrict__ xn,
                             const float* __restrict__ W1,
                             const float* __restrict__ W2,
                             const float* __restrict__ as1,
                             const float* __restrict__ ad1,
                             const float* __restrict__ as2,
                             const float* __restrict__ ad2) {
    int i = blockIdx.x * 256 + threadIdx.x;
    if (i < (NN * 256) / 4) {
        float4 a = reinterpret_cast<const float4*>(xn)[i];
        reinterpret_cast<__half2*>(g_xa16)[i * 2]     = __floats2half2_rn(a.x, a.y);
        reinterpret_cast<__half2*>(g_xa16)[i * 2 + 1] = __floats2half2_rn(a.z, a.w);
    }
    if (i < 256 * 256) {
        int k = i >> 8, n = i & 255;
        g_w1t16[n * 256 + k] = __float2half_rn(W1[k * 256 + n]);
    }
    if (i < 256 * 64) {
        int k = i >> 6, n = i & 63;
        g_w2t16[n * 256 + k] = __float2half_rn(W2[k * 64 + n]);
    }
    // augmented layer1 logit columns
    if (i < 256 * 8) {
        int k = i >> 3, j = i & 7;
        int h = j & 3;
        const float* av = (j < 4) ? as1 : ad1;
        float s = 0.f;
        #pragma unroll 8
        for (int c = 0; c < 64; c++)
            s += W1[k * 256 + h * 64 + c] * av[h * 64 + c];
        g_w1t16[(256 + j) * 256 + k] = __float2half_rn(s);
    }
    // augmented layer2 logit columns
    if (i < 256 * 2) {
        int k = i >> 1, j = i & 1;
        const float* av = j ? ad2 : as2;
        float s = 0.f;
        #pragma unroll 8
        for (int c = 0; c < 64; c++)
            s += W2[k * 64 + c] * av[c];
        g_w2t16[(64 + j) * 256 + k] = __float2half_rn(s);
    }
}

// ------- prep C: xc16 only ---------------------------------------------------
__global__ void cvt_c_kernel(const float* __restrict__ xc) {
    int i = blockIdx.x * 256 + threadIdx.x;
    if (i < (NN * 256) / 4) {
        float4 b = reinterpret_cast<const float4*>(xc)[i];
        reinterpret_cast<__half2*>(g_xc16)[i * 2]     = __floats2half2_rn(b.x, b.y);
        reinterpret_cast<__half2*>(g_xc16)[i * 2 + 1] = __floats2half2_rn(b.z, b.w);
    }
}

// ---------------- CSR build ------------------------------------------------
__global__ void init_deg_kernel(int n) {
    int i = blockIdx.x * blockDim.x + threadIdx.x;
    if (i < n) g_deg[i] = 1;   // self-loop
}

__global__ void count_kernel(const int* __restrict__ edst, int e) {
    int i = blockIdx.x * blockDim.x + threadIdx.x;
    if (i < e) atomicAdd(&g_deg[edst[i]], 1);
}

__global__ void scan_local_kernel(int n) {
    __shared__ int ws[9];
    int tid = threadIdx.x, lane = tid & 31, w = tid >> 5;
    int i = blockIdx.x * 256 + tid;
    int v = (i < n) ? g_deg[i] : 0;
    int x = v;
    #pragma unroll
    for (int o = 1; o < 32; o <<= 1) {
        int y = __shfl_up_sync(0xffffffffu, x, o);
        if (lane >= o) x += y;
    }
    if (lane == 31) ws[w] = x;
    __syncthreads();
    if (tid == 0) {
        int s = 0;
        #pragma unroll
        for (int q = 0; q < 8; q++) { int t = ws[q]; ws[q] = s; s += t; }
        g_bsum[blockIdx.x] = s;
    }
    __syncthreads();
    if (i < n) g_offs[i] = ws[w] + x - v;
}

__global__ void scan_bsum_kernel(int nb, int n) {
    __shared__ int wtot[8];
    int tid = threadIdx.x, lane = tid & 31, w = tid >> 5;
    int v = (tid < nb) ? g_bsum[tid] : 0;
    int x = v;
    #pragma unroll
    for (int o = 1; o < 32; o <<= 1) {
        int y = __shfl_up_sync(0xffffffffu, x, o);
        if (lane >= o) x += y;
    }
    if (lane == 31) wtot[w] = x;
    __syncthreads();
    int pre = 0;
    #pragma unroll
    for (int q = 0; q < 8; q++) pre += (q < w) ? wtot[q] : 0;
    if (tid < nb) g_bpre[tid] = pre + x - v;
    if (tid == nb - 1) g_offs[n] = pre + x;
}

__global__ void scan_add_place_kernel(int n) {
    int i = blockIdx.x * 256 + threadIdx.x;
    if (i < n) {
        int o = g_offs[i] + (blockIdx.x > 0 ? g_bpre[blockIdx.x] : 0);
        g_offs[i] = o;
        g_ssrc[o] = i;       // self-loop first
        g_cur[i] = o + 1;
    }
}

__global__ void scatter_kernel(const int* __restrict__ esrc,
                               const int* __restrict__ edst, int e) {
    int i = blockIdx.x * blockDim.x + threadIdx.x;
    if (i < e) {
        int d = edst[i];
        int pos = atomicAdd(&g_cur[d], 1);
        g_ssrc[pos] = esrc[i];
    }
}

// ---------------- FP16 tensor-core GEMM, 128x128 tile, 2-stage cp.async ----
__device__ __forceinline__ uint32_t smem_u32(const void* p) {
    uint32_t a;
    asm("{ .reg .u64 t; cvta.to.shared.u64 t, %1; cvt.u32.u64 %0, t; }"
        : "=r"(a) : "l"(p));
    return a;
}
__device__ __forceinline__ void cp16(uint32_t dst, const void* src, int srcsz) {
    asm volatile("cp.async.cg.shared.global [%0], [%1], 16, %2;"
                 :: "r"(dst), "l"(src), "r"(srcsz));
}
__device__ __forceinline__ void cp_commit() {
    asm volatile("cp.async.commit_group;");
}
template <int N>
__device__ __forceinline__ void cp_wait() {
    asm volatile("cp.async.wait_group %0;" :: "n"(N));
}
__device__ __forceinline__ void ldsm_x4(unsigned& r0, unsigned& r1,
                                        unsigned& r2, unsigned& r3, uint32_t a) {
    asm volatile("ldmatrix.sync.aligned.m8n8.x4.shared.b16 {%0,%1,%2,%3}, [%4];"
                 : "=r"(r0), "=r"(r1), "=r"(r2), "=r"(r3) : "r"(a));
}
__device__ __forceinline__ void mma_f16(float* c, const unsigned* a,
                                        const unsigned* b) {
    asm volatile(
        "mma.sync.aligned.m16n8k16.row.col.f32.f16.f16.f32 "
        "{%0,%1,%2,%3}, {%4,%5,%6,%7}, {%8,%9}, {%0,%1,%2,%3};\n"
        : "+f"(c[0]), "+f"(c[1]), "+f"(c[2]), "+f"(c[3])
        : "r"(a[0]), "r"(a[1]), "r"(a[2]), "r"(a[3]), "r"(b[0]), "r"(b[1]));
}

// C[m_base+.., NC] = A16 @ B16t^T. Tile 128x128x64, 8 warps (2x4).
// Columns >= NC: aug logits (augsel 0=layer1, 1=layer2) or discarded.
template <int EPI, bool C16>
__global__ void __launch_bounds__(256, 2) gemm_f16(
    int asel, int bsel, const float* __restrict__ bias, int csel,
    int M, int NC, int augsel, int m_base) {
    const __half* A = (asel == 0) ? g_xa16
                    : (asel == 1) ? g_xc16
                    : (asel == 2) ? g_hs16
                                  : g_h16;
    const __half* Bt = bsel ? g_w2t16 : g_w1t16;
    __half* Ch = (csel == 1) ? g_xp1h : (csel == 2) ? g_hs16 : g_xp2h;
    float* Cf = g_skip;

    extern __shared__ __half dynsm[];
    __half* As = dynsm;
    __half* Bs = dynsm + 2 * 128 * 72;
    const int ASTG = 128 * 72, BSTG = 128 * 72;

    int tid = threadIdx.x;
    int wid = tid >> 5, lane = tid & 31;
    int g = lane >> 2, t4 = lane & 3;
    int wm = (wid >> 2) * 64;
    int wn = (wid & 3) * 32;
    int m0 = m_base + blockIdx.x * 128;
    int n0 = blockIdx.y * 128;

    uint32_t aA = smem_u32(As), aB = smem_u32(Bs);

    int a_row_off = (lane & 7) + ((lane >> 3) & 1) * 8;
    int a_col_off = ((lane >> 4) & 1) * 8;
    int b_row_off = (lane & 7) + ((lane >> 4) & 1) * 8;
    int b_col_off = ((lane >> 3) & 1) * 8;

    float acc[4][4][4];
    #pragma unroll
    for (int mt = 0; mt < 4; mt++)
        #pragma unroll
        for (int nt = 0; nt < 4; nt++)
            #pragma unroll
            for (int q = 0; q < 4; q++) acc[mt][nt][q] = 0.f;

    auto load_chunk = [&](int ch, int st) {
        int k0 = ch * 64;
        #pragma unroll
        for (int i = 0; i < 4; i++) {
            int lin = tid + i * 256;
            int row = lin >> 3, seg = lin & 7;
            uint32_t dst = aA + (uint32_t)(st * ASTG + row * 72 + seg * 8) * 2u;
            const __half* src = &A[(size_t)(m0 + row) * 256 + k0 + seg * 8];
            cp16(dst, src, (m0 + row < M) ? 16 : 0);
        }
        #pragma unroll
        for (int i = 0; i < 4; i++) {
            int lin = tid + i * 256;
            int row = lin >> 3, seg = lin & 7;
            uint32_t dst = aB + (uint32_t)(st * BSTG + row * 72 + seg * 8) * 2u;
            const __half* src = &Bt[(size_t)(n0 + row) * 256 + k0 + seg * 8];
            cp16(dst, src, 16);
        }
        cp_commit();
    };

    load_chunk(0, 0);

    #pragma unroll
    for (int ch = 0; ch < 4; ch++) {
        int st = ch & 1;
        if (ch < 3) {
            load_chunk(ch + 1, st ^ 1);
            cp_wait<1>();
        } else {
            cp_wait<0>();
        }
        __syncthreads();

        uint32_t baseA = aA + (uint32_t)(st * ASTG) * 2u;
        uint32_t baseB = aB + (uint32_t)(st * BSTG) * 2u;
        #pragma unroll
        for (int ks = 0; ks < 4; ks++) {
            int kb = ks * 16;
            unsigned a[4][4], b[4][2];
            #pragma unroll
            for (int mt = 0; mt < 4; mt++) {
                uint32_t ad = baseA +
                    (uint32_t)((wm + mt * 16 + a_row_off) * 72 + kb + a_col_off) * 2u;
                ldsm_x4(a[mt][0], a[mt][1], a[mt][2], a[mt][3], ad);
            }
            #pragma unroll
            for (int p = 0; p < 2; p++) {
                uint32_t bd = baseB +
                    (uint32_t)((wn + p * 16 + b_row_off) * 72 + kb + b_col_off) * 2u;
                ldsm_x4(b[2 * p][0], b[2 * p][1], b[2 * p + 1][0], b[2 * p + 1][1], bd);
            }
            #pragma unroll
            for (int mt = 0; mt < 4; mt++)
                #pragma unroll
                for (int nt = 0; nt < 4; nt++)
                    mma_f16(acc[mt][nt], a[mt], b[nt]);
        }
        __syncthreads();
    }

    // epilogue (per-column guards for partial / aug tiles)
    #pragma unroll
    for (int mt = 0; mt < 4; mt++) {
        #pragma unroll
        for (int half = 0; half < 2; half++) {
            int row = m0 + wm + mt * 16 + g + half * 8;
            if (row >= M) continue;
            #pragma unroll
            for (int nt = 0; nt < 4; nt++) {
                int col = n0 + wn + nt * 8 + 2 * t4;
                float v0 = acc[mt][nt][half * 2 + 0];
                float v1 = acc[mt][nt][half * 2 + 1];
                int c = col - NC;
                if (c >= 0) {
                    if (augsel == 0 && c < 8) {
                        if (c < 4) g_als1[(size_t)row * 4 + c] = v0;
                        else       g_ald1[(size_t)row * 4 + c - 4] = v0;
                        int c1 = c + 1;
                        if (c1 < 4) g_als1[(size_t)row * 4 + c1] = v1;
                        else        g_ald1[(size_t)row * 4 + c1 - 4] = v1;
                    } else if (augsel == 1 && c == 0) {
                        g_als2[row] = v0; g_ald2[row] = v1;
                    }
                    continue;
                }
                if (EPI) {
                    v0 += bias[col];
                    v1 += bias[col + 1];
                    if (EPI == 1) {
                        v0 = fmaxf(v0, 0.f);
                        v1 = fmaxf(v1, 0.f);
                    }
                }
                if (C16) {
                    *reinterpret_cast<__half2*>(&Ch[(size_t)row * NC + col]) =
                        __floats2half2_rn(v0, v1);
                } else {
                    *reinterpret_cast<float2*>(&Cf[(size_t)row * NC + col]) =
                        make_float2(v0, v1);
                }
            }
        }
    }
}

// ---------------- layer1 aggregation: one warp per node (R9-proven loop) ----
__global__ void agg1_kernel(const float* __restrict__ b1, int base, int nmax) {
    int node = base + blockIdx.x * 8 + (threadIdx.x >> 5);
    if (node >= nmax) return;
    int lane = threadIdx.x & 31;
    int h = lane >> 3;
    int beg = g_offs[node], end = g_offs[node + 1];
    float adn = g_ald1[node * 4 + h];
    float m = -1e30f, ssum = 0.f;
    float acc[8];
    #pragma unroll
    for (int q = 0; q < 8; q++) acc[q] = 0.f;

    for (int j = beg; j < end; j++) {
        int s = g_ssrc[j];
        float a = g_als1[s * 4 + h] + adn;
        a = (a > 0.f) ? a : 0.2f * a;
        if (a > m) {
            float sc = __expf(m - a);
            ssum *= sc;
            #pragma unroll
            for (int q = 0; q < 8; q++) acc[q] *= sc;
            m = a;
        }
        float w = __expf(a - m);
        ssum += w;
        uint4 u = *reinterpret_cast<const uint4*>(
            &g_xp1h[(size_t)s * 256 + lane * 8]);
        float2 f0 = __half22float2(*reinterpret_cast<__half2*>(&u.x));
        float2 f1 = __half22float2(*reinterpret_cast<__half2*>(&u.y));
        float2 f2 = __half22float2(*reinterpret_cast<__half2*>(&u.z));
        float2 f3 = __half22float2(*reinterpret_cast<__half2*>(&u.w));
        acc[0] = fmaf(w, f0.x, acc[0]);
        acc[1] = fmaf(w, f0.y, acc[1]);
        acc[2] = fmaf(w, f1.x, acc[2]);
        acc[3] = fmaf(w, f1.y, acc[3]);
        acc[4] = fmaf(w, f2.x, acc[4]);
        acc[5] = fmaf(w, f2.y, acc[5]);
        acc[6] = fmaf(w, f3.x, acc[6]);
        acc[7] = fmaf(w, f3.y, acc[7]);
    }
    float inv = 1.f / ssum;
    int col = lane * 8;
    float o[8];
    #pragma unroll
    for (int q = 0; q < 8; q++) {
        float x = acc[q] * inv + b1[col + q];
        o[q] = (x > 0.f) ? x : expm1f(x);   // elu
    }
    __half2* dst = reinterpret_cast<__half2*>(&g_h16[(size_t)node * 256 + col]);
    dst[0] = __floats2half2_rn(o[0], o[1]);
    dst[1] = __floats2half2_rn(o[2], o[3]);
    dst[2] = __floats2half2_rn(o[4], o[5]);
    dst[3] = __floats2half2_rn(o[6], o[7]);
}

// ---------------- layer2 aggregation ---------------------------------------
__global__ void agg2_kernel(const float* __restrict__ b2,
                            float* __restrict__ out, int n) {
    int node = blockIdx.x * 8 + (threadIdx.x >> 5);
    if (node >= n) return;
    int lane = threadIdx.x & 31;
    int beg = g_offs[node], end = g_offs[node + 1];
    float adn = g_ald2[node];
    float m = -1e30f, ssum = 0.f, ax = 0.f, ay = 0.f;
    for (int j = beg; j < end; j++) {
        int s = g_ssrc[j];
        float a = g_als2[s] + adn;
        a = (a > 0.f) ? a : 0.2f * a;
        if (a > m) {
            float sc = __expf(m - a);
            ax *= sc; ay *= sc; ssum *= sc; m = a;
        }
        float w = __expf(a - m);
        ssum += w;
        float2 v = __half22float2(*reinterpret_cast<const __half2*>(
            &g_xp2h[(size_t)s * 64 + lane * 2]));
        ax = fmaf(w, v.x, ax);
        ay = fmaf(w, v.y, ay);
    }
    float inv = 1.f / ssum;
    int col = lane * 2;
    out[(size_t)node * 64 + col] =
        ax * inv + b2[col] + g_skip[(size_t)node * 64 + col];
    out[(size_t)node * 64 + col + 1] =
        ay * inv + b2[col + 1] + g_skip[(size_t)node * 64 + col + 1];
}

// ---------------- launch (three streams, event fork/join) -------------------
extern "C" void kernel_launch(void* const* d_in, const int* in_sizes, int n_in,
                              void* d_out, int out_size) {
    const float* x_clean  = (const float*)d_in[0];
    const float* x_noised = (const float*)d_in[1];
    const int*   esrc     = (const int*)d_in[2];
    const int*   edst     = (const int*)d_in[3];
    const float* W1  = (const float*)d_in[4];
    const float* as1 = (const float*)d_in[5];
    const float* ad1 = (const float*)d_in[6];
    const float* b1  = (const float*)d_in[7];
    const float* W2  = (const float*)d_in[8];
    const float* as2 = (const float*)d_in[9];
    const float* ad2 = (const float*)d_in[10];
    const float* b2  = (const float*)d_in[11];
    float* out = (float*)d_out;

    int N = in_sizes[0] / 256;  // 50000
    int E = in_sizes[2];        // 800000

    static cudaStream_t s1 = nullptr, s2 = nullptr;
    static cudaEvent_t evRoot, evCvtA, evCsr, evSkip, evA1a, evX2a;
    if (s1 == nullptr) {
        cudaStreamCreateWithFlags(&s1, cudaStreamNonBlocking);
        cudaStreamCreateWithFlags(&s2, cudaStreamNonBlocking);
        cudaEventCreateWithFlags(&evRoot, cudaEventDisableTiming);
        cudaEventCreateWithFlags(&evCvtA, cudaEventDisableTiming);
        cudaEventCreateWithFlags(&evCsr,  cudaEventDisableTiming);
        cudaEventCreateWithFlags(&evSkip, cudaEventDisableTiming);
        cudaEventCreateWithFlags(&evA1a,  cudaEventDisableTiming);
        cudaEventCreateWithFlags(&evX2a,  cudaEventDisableTiming);
        const int SMBi = (2 * 128 * 72 + 2 * 128 * 72) * 2;
        cudaFuncSetAttribute(gemm_f16<0, true>,  cudaFuncAttributeMaxDynamicSharedMemorySize, SMBi);
        cudaFuncSetAttribute(gemm_f16<1, true>,  cudaFuncAttributeMaxDynamicSharedMemorySize, SMBi);
        cudaFuncSetAttribute(gemm_f16<2, false>, cudaFuncAttributeMaxDynamicSharedMemorySize, SMBi);
    }
    const int SMB = (2 * 128 * 72 + 2 * 128 * 72) * 2;  // 73728 B

    int nb = (N + 255) / 256;        // 196
    int mtiles = (N + 127) / 128;    // 391
    int N2 = 25088;                  // chunk boundary (196 * 128)
    int mt_a = N2 / 128;             // 196 tiles, rows [0, 25088)
    int mt_b = (N - N2 + 127) / 128; // 195 tiles, rows [25088, 50000)

    // fork s1, s2 from capture stream
    cudaEventRecord(evRoot, 0);
    cudaStreamWaitEvent(s1, evRoot, 0);
    cudaStreamWaitEvent(s2, evRoot, 0);

    // s0: xa16+weights, then xp1 GEMM (y=3 incl. aug logits1)
    cvt_a_kernel<<<(NN * 256 / 4 + 255) / 256, 256>>>(
        x_noised, W1, W2, as1, ad1, as2, ad2);                                   // 1
    cudaEventRecord(evCvtA, 0);
    gemm_f16<0, true><<<dim3(mtiles, 3), 256, SMB>>>(0, 0, nullptr, 1, N, 256, 0, 0); // 2: xp1+logits1

    // s2: xc16 -> hs -> skip
    cvt_c_kernel<<<(NN * 256 / 4 + 255) / 256, 256, 0, s2>>>(x_clean);           // 3
    cudaStreamWaitEvent(s2, evCvtA, 0);
    gemm_f16<1, true><<<dim3(mtiles, 2), 256, SMB, s2>>>(1, 0, b1, 2, N, 256, -1, 0);  // 4: hs
    gemm_f16<2, false><<<dim3(mtiles, 1), 256, SMB, s2>>>(2, 1, b2, 3, N, 64, -1, 0);  // 5: skip
    cudaEventRecord(evSkip, s2);

    // s1: CSR build chain (fully independent)
    init_deg_kernel<<<nb, 256, 0, s1>>>(N);                                      // 6
    count_kernel<<<(E + 255) / 256, 256, 0, s1>>>(edst, E);                      // 7
    scan_local_kernel<<<nb, 256, 0, s1>>>(N);                                    // 8
    scan_bsum_kernel<<<1, 256, 0, s1>>>(nb, N);                                  // 9
    scan_add_place_kernel<<<nb, 256, 0, s1>>>(N);                                // 10
    scatter_kernel<<<(E + 255) / 256, 256, 0, s1>>>(esrc, edst, E);              // 11
    cudaEventRecord(evCsr, s1);

    // s0: agg1 chunk A [0, N2), then chunk B [N2, N)
    cudaStreamWaitEvent(0, evCsr, 0);
    agg1_kernel<<<N2 / 8, 256>>>(b1, 0, N2);                                     // 12
    cudaEventRecord(evA1a, 0);
    agg1_kernel<<<(N - N2 + 7) / 8, 256>>>(b1, N2, N);                           // 13

    // s2: xp2 chunk A overlaps agg1 chunk B
    cudaStreamWaitEvent(s2, evA1a, 0);
    gemm_f16<0, true><<<dim3(mt_a, 2), 256, SMB, s2>>>(3, 1, nullptr, 4, N2, 64, 1, 0);  // 14: xp2a+logits2a
    cudaEventRecord(evX2a, s2);

    // s0: xp2 chunk B, then agg2 (needs xp2a+xp2b+skip)
    gemm_f16<0, true><<<dim3(mt_b, 2), 256, SMB>>>(3, 1, nullptr, 4, N, 64, 1, N2);      // 15: xp2b+logits2b
    cudaStreamWaitEvent(0, evX2a, 0);
    cudaStreamWaitEvent(0, evSkip, 0);
    agg2_kernel<<<(N + 7) / 8, 256>>>(b2, out, N);                               // 16
}

// round 15
// speedup vs baseline: 1.0956x; 1.0956x over previous
#include <cuda_runtime.h>
#include <cuda_fp16.h>
#include <cstdint>
#include <cstddef>

#define NN 50000
#define EE 800000
#define ET (EE + NN)

// ---------------- scratch (device globals; no allocation allowed) ----------
__device__ __align__(16) __half g_xp1h[(size_t)NN * 256];
__device__ __align__(16) __half g_xp2h[(size_t)NN * 64];
__device__ __align__(16) float  g_skip[(size_t)NN * 64];
__device__ __align__(16) __half g_xa16[(size_t)NN * 256];
__device__ __align__(16) __half g_xc16[(size_t)NN * 256];
__device__ __align__(16) __half g_h16[(size_t)NN * 256];
__device__ __align__(16) __half g_hs16[(size_t)NN * 256];
__device__ __align__(16) __half g_w1t16[384 * 256];        // W1^T fp16 + 8 aug rows (padded)
__device__ __align__(16) __half g_w2t16[128 * 256];        // W2^T fp16 + 2 aug rows (padded)
__device__ __align__(16) float g_als1[(size_t)NN * 4];
__device__ __align__(16) float g_ald1[(size_t)NN * 4];
__device__ __align__(16) float g_als2[NN];
__device__ __align__(16) float g_ald2[NN];
__device__ int g_deg[NN];
__device__ int g_offs[NN + 1];
__device__ int g_cur[NN];
__device__ int g_ssrc[ET];
__device__ int g_bsum[256];
__device__ int g_bpre[256];

// ------- prep A: xa16 + weight tables + aug logit columns -------------------
__global__ void cvt_a_kernel(const float* __restrict__ xn,
                             const float* __restrict__ W1,
                             const float* __restrict__ W2,
                             const float* __restrict__ as1,
                             const float* __restrict__ ad1,
                             const float* __restrict__ as2,
                             const float* __restrict__ ad2) {
    int i = blockIdx.x * 256 + threadIdx.x;
    if (i < (NN * 256) / 4) {
        float4 a = reinterpret_cast<const float4*>(xn)[i];
        reinterpret_cast<__half2*>(g_xa16)[i * 2]     = __floats2half2_rn(a.x, a.y);
        reinterpret_cast<__half2*>(g_xa16)[i * 2 + 1] = __floats2half2_rn(a.z, a.w);
    }
    if (i < 256 * 256) {
        int k = i >> 8, n = i & 255;
        g_w1t16[n * 256 + k] = __float2half_rn(W1[k * 256 + n]);
    }
    if (i < 256 * 64) {
        int k = i >> 6, n = i & 63;
        g_w2t16[n * 256 + k] = __float2half_rn(W2[k * 64 + n]);
    }
    // augmented layer1 logit columns
    if (i < 256 * 8) {
        int k = i >> 3, j = i & 7;
        int h = j & 3;
        const float* av = (j < 4) ? as1 : ad1;
        float s = 0.f;
        #pragma unroll 8
        for (int c = 0; c < 64; c++)
            s += W1[k * 256 + h * 64 + c] * av[h * 64 + c];
        g_w1t16[(256 + j) * 256 + k] = __float2half_rn(s);
    }
    // augmented layer2 logit columns
    if (i < 256 * 2) {
        int k = i >> 1, j = i & 1;
        const float* av = j ? ad2 : as2;
        float s = 0.f;
        #pragma unroll 8
        for (int c = 0; c < 64; c++)
            s += W2[k * 64 + c] * av[c];
        g_w2t16[(64 + j) * 256 + k] = __float2half_rn(s);
    }
}

// ------- prep C: xc16 only ---------------------------------------------------
__global__ void cvt_c_kernel(const float* __restrict__ xc) {
    int i = blockIdx.x * 256 + threadIdx.x;
    if (i < (NN * 256) / 4) {
        float4 b = reinterpret_cast<const float4*>(xc)[i];
        reinterpret_cast<__half2*>(g_xc16)[i * 2]     = __floats2half2_rn(b.x, b.y);
        reinterpret_cast<__half2*>(g_xc16)[i * 2 + 1] = __floats2half2_rn(b.z, b.w);
    }
}

// ---------------- CSR build ------------------------------------------------
__global__ void init_deg_kernel(int n) {
    int i = blockIdx.x * blockDim.x + threadIdx.x;
    if (i < n) g_deg[i] = 1;   // self-loop
}

__global__ void count_kernel(const int* __restrict__ edst, int e) {
    int i = blockIdx.x * blockDim.x + threadIdx.x;
    if (i < e) atomicAdd(&g_deg[edst[i]], 1);
}

__global__ void scan_local_kernel(int n) {
    __shared__ int ws[9];
    int tid = threadIdx.x, lane = tid & 31, w = tid >> 5;
    int i = blockIdx.x * 256 + tid;
    int v = (i < n) ? g_deg[i] : 0;
    int x = v;
    #pragma unroll
    for (int o = 1; o < 32; o <<= 1) {
        int y = __shfl_up_sync(0xffffffffu, x, o);
        if (lane >= o) x += y;
    }
    if (lane == 31) ws[w] = x;
    __syncthreads();
    if (tid == 0) {
        int s = 0;
        #pragma unroll
        for (int q = 0; q < 8; q++) { int t = ws[q]; ws[q] = s; s += t; }
        g_bsum[blockIdx.x] = s;
    }
    __syncthreads();
    if (i < n) g_offs[i] = ws[w] + x - v;
}

__global__ void scan_bsum_kernel(int nb, int n) {
    __shared__ int wtot[8];
    int tid = threadIdx.x, lane = tid & 31, w = tid >> 5;
    int v = (tid < nb) ? g_bsum[tid] : 0;
    int x = v;
    #pragma unroll
    for (int o = 1; o < 32; o <<= 1) {
        int y = __shfl_up_sync(0xffffffffu, x, o);
        if (lane >= o) x += y;
    }
    if (lane == 31) wtot[w] = x;
    __syncthreads();
    int pre = 0;
    #pragma unroll
    for (int q = 0; q < 8; q++) pre += (q < w) ? wtot[q] : 0;
    if (tid < nb) g_bpre[tid] = pre + x - v;
    if (tid == nb - 1) g_offs[n] = pre + x;
}

__global__ void scan_add_place_kernel(int n) {
    int i = blockIdx.x * 256 + threadIdx.x;
    if (i < n) {
        int o = g_offs[i] + (blockIdx.x > 0 ? g_bpre[blockIdx.x] : 0);
        g_offs[i] = o;
        g_ssrc[o] = i;       // self-loop first
        g_cur[i] = o + 1;
    }
}

__global__ void scatter_kernel(const int* __restrict__ esrc,
                               const int* __restrict__ edst, int e) {
    int i = blockIdx.x * blockDim.x + threadIdx.x;
    if (i < e) {
        int d = edst[i];
        int pos = atomicAdd(&g_cur[d], 1);
        g_ssrc[pos] = esrc[i];
    }
}

// ---------------- FP16 tensor-core GEMM, 128x128 tile, 2-stage cp.async ----
__device__ __forceinline__ uint32_t smem_u32(const void* p) {
    uint32_t a;
    asm("{ .reg .u64 t; cvta.to.shared.u64 t, %1; cvt.u32.u64 %0, t; }"
        : "=r"(a) : "l"(p));
    return a;
}
__device__ __forceinline__ void cp16(uint32_t dst, const void* src, int srcsz) {
    asm volatile("cp.async.cg.shared.global [%0], [%1], 16, %2;"
                 :: "r"(dst), "l"(src), "r"(srcsz));
}
__device__ __forceinline__ void cp_commit() {
    asm volatile("cp.async.commit_group;");
}
template <int N>
__device__ __forceinline__ void cp_wait() {
    asm volatile("cp.async.wait_group %0;" :: "n"(N));
}
__device__ __forceinline__ void ldsm_x4(unsigned& r0, unsigned& r1,
                                        unsigned& r2, unsigned& r3, uint32_t a) {
    asm volatile("ldmatrix.sync.aligned.m8n8.x4.shared.b16 {%0,%1,%2,%3}, [%4];"
                 : "=r"(r0), "=r"(r1), "=r"(r2), "=r"(r3) : "r"(a));
}
__device__ __forceinline__ void mma_f16(float* c, const unsigned* a,
                                        const unsigned* b) {
    asm volatile(
        "mma.sync.aligned.m16n8k16.row.col.f32.f16.f16.f32 "
        "{%0,%1,%2,%3}, {%4,%5,%6,%7}, {%8,%9}, {%0,%1,%2,%3};\n"
        : "+f"(c[0]), "+f"(c[1]), "+f"(c[2]), "+f"(c[3])
        : "r"(a[0]), "r"(a[1]), "r"(a[2]), "r"(a[3]), "r"(b[0]), "r"(b[1]));
}

// C[M,NC] = A16[M,256] @ B16t[rows,256]^T. Tile 128x128x64, 8 warps (2x4).
// Columns >= NC: aug logits (augsel 0=layer1, 1=layer2) or discarded.
template <int EPI, bool C16>
__global__ void __launch_bounds__(256, 2) gemm_f16(
    int asel, int bsel, const float* __restrict__ bias, int csel,
    int M, int NC, int augsel) {
    const __half* A = (asel == 0) ? g_xa16
                    : (asel == 1) ? g_xc16
                    : (asel == 2) ? g_hs16
                                  : g_h16;
    const __half* Bt = bsel ? g_w2t16 : g_w1t16;
    __half* Ch = (csel == 1) ? g_xp1h : (csel == 2) ? g_hs16 : g_xp2h;
    float* Cf = g_skip;

    extern __shared__ __half dynsm[];
    __half* As = dynsm;
    __half* Bs = dynsm + 2 * 128 * 72;
    const int ASTG = 128 * 72, BSTG = 128 * 72;

    int tid = threadIdx.x;
    int wid = tid >> 5, lane = tid & 31;
    int g = lane >> 2, t4 = lane & 3;
    int wm = (wid >> 2) * 64;
    int wn = (wid & 3) * 32;
    int m0 = blockIdx.x * 128;
    int n0 = blockIdx.y * 128;

    uint32_t aA = smem_u32(As), aB = smem_u32(Bs);

    int a_row_off = (lane & 7) + ((lane >> 3) & 1) * 8;
    int a_col_off = ((lane >> 4) & 1) * 8;
    int b_row_off = (lane & 7) + ((lane >> 4) & 1) * 8;
    int b_col_off = ((lane >> 3) & 1) * 8;

    float acc[4][4][4];
    #pragma unroll
    for (int mt = 0; mt < 4; mt++)
        #pragma unroll
        for (int nt = 0; nt < 4; nt++)
            #pragma unroll
            for (int q = 0; q < 4; q++) acc[mt][nt][q] = 0.f;

    auto load_chunk = [&](int ch, int st) {
        int k0 = ch * 64;
        #pragma unroll
        for (int i = 0; i < 4; i++) {
            int lin = tid + i * 256;
            int row = lin >> 3, seg = lin & 7;
            uint32_t dst = aA + (uint32_t)(st * ASTG + row * 72 + seg * 8) * 2u;
            const __half* src = &A[(size_t)(m0 + row) * 256 + k0 + seg * 8];
            cp16(dst, src, (m0 + row < M) ? 16 : 0);
        }
        #pragma unroll
        for (int i = 0; i < 4; i++) {
            int lin = tid + i * 256;
            int row = lin >> 3, seg = lin & 7;
            uint32_t dst = aB + (uint32_t)(st * BSTG + row * 72 + seg * 8) * 2u;
            const __half* src = &Bt[(size_t)(n0 + row) * 256 + k0 + seg * 8];
            cp16(dst, src, 16);
        }
        cp_commit();
    };

    load_chunk(0, 0);

    #pragma unroll
    for (int ch = 0; ch < 4; ch++) {
        int st = ch & 1;
        if (ch < 3) {
            load_chunk(ch + 1, st ^ 1);
            cp_wait<1>();
        } else {
            cp_wait<0>();
        }
        __syncthreads();

        uint32_t baseA = aA + (uint32_t)(st * ASTG) * 2u;
        uint32_t baseB = aB + (uint32_t)(st * BSTG) * 2u;
        #pragma unroll
        for (int ks = 0; ks < 4; ks++) {
            int kb = ks * 16;
            unsigned a[4][4], b[4][2];
            #pragma unroll
            for (int mt = 0; mt < 4; mt++) {
                uint32_t ad = baseA +
                    (uint32_t)((wm + mt * 16 + a_row_off) * 72 + kb + a_col_off) * 2u;
                ldsm_x4(a[mt][0], a[mt][1], a[mt][2], a[mt][3], ad);
            }
            #pragma unroll
            for (int p = 0; p < 2; p++) {
                uint32_t bd = baseB +
                    (uint32_t)((wn + p * 16 + b_row_off) * 72 + kb + b_col_off) * 2u;
                ldsm_x4(b[2 * p][0], b[2 * p][1], b[2 * p + 1][0], b[2 * p + 1][1], bd);
            }
            #pragma unroll
            for (int mt = 0; mt < 4; mt++)
                #pragma unroll
                for (int nt = 0; nt < 4; nt++)
                    mma_f16(acc[mt][nt], a[mt], b[nt]);
        }
        __syncthreads();
    }

    // epilogue (per-column guards for partial / aug tiles)
    #pragma unroll
    for (int mt = 0; mt < 4; mt++) {
        #pragma unroll
        for (int half = 0; half < 2; half++) {
            int row = m0 + wm + mt * 16 + g + half * 8;
            if (row >= M) continue;
            #pragma unroll
            for (int nt = 0; nt < 4; nt++) {
                int col = n0 + wn + nt * 8 + 2 * t4;
                float v0 = acc[mt][nt][half * 2 + 0];
                float v1 = acc[mt][nt][half * 2 + 1];
                int c = col - NC;
                if (c >= 0) {
                    if (augsel == 0 && c < 8) {
                        if (c < 4) g_als1[(size_t)row * 4 + c] = v0;
                        else       g_ald1[(size_t)row * 4 + c - 4] = v0;
                        int c1 = c + 1;
                        if (c1 < 4) g_als1[(size_t)row * 4 + c1] = v1;
                        else        g_ald1[(size_t)row * 4 + c1 - 4] = v1;
                    } else if (augsel == 1 && c == 0) {
                        g_als2[row] = v0; g_ald2[row] = v1;
                    }
                    continue;
                }
                if (EPI) {
                    v0 += bias[col];
                    v1 += bias[col + 1];
                    if (EPI == 1) {
                        v0 = fmaxf(v0, 0.f);
                        v1 = fmaxf(v1, 0.f);
                    }
                }
                if (C16) {
                    *reinterpret_cast<__half2*>(&Ch[(size_t)row * NC + col]) =
                        __floats2half2_rn(v0, v1);
                } else {
                    *reinterpret_cast<float2*>(&Cf[(size_t)row * NC + col]) =
                        make_float2(v0, v1);
                }
            }
        }
    }
}

// ---------------- layer1 aggregation: one warp per node (R9-proven loop) ----
__global__ void agg1_kernel(const float* __restrict__ b1, int n) {
    int node = blockIdx.x * 8 + (threadIdx.x >> 5);
    if (node >= n) return;
    int lane = threadIdx.x & 31;
    int h = lane >> 3;
    int beg = g_offs[node], end = g_offs[node + 1];
    float adn = g_ald1[node * 4 + h];
    float m = -1e30f, ssum = 0.f;
    float acc[8];
    #pragma unroll
    for (int q = 0; q < 8; q++) acc[q] = 0.f;

    for (int j = beg; j < end; j++) {
        int s = g_ssrc[j];
        float a = g_als1[s * 4 + h] + adn;
        a = (a > 0.f) ? a : 0.2f * a;
        if (a > m) {
            float sc = __expf(m - a);
            ssum *= sc;
            #pragma unroll
            for (int q = 0; q < 8; q++) acc[q] *= sc;
            m = a;
        }
        float w = __expf(a - m);
        ssum += w;
        uint4 u = *reinterpret_cast<const uint4*>(
            &g_xp1h[(size_t)s * 256 + lane * 8]);
        float2 f0 = __half22float2(*reinterpret_cast<__half2*>(&u.x));
        float2 f1 = __half22float2(*reinterpret_cast<__half2*>(&u.y));
        float2 f2 = __half22float2(*reinterpret_cast<__half2*>(&u.z));
        float2 f3 = __half22float2(*reinterpret_cast<__half2*>(&u.w));
        acc[0] = fmaf(w, f0.x, acc[0]);
        acc[1] = fmaf(w, f0.y, acc[1]);
        acc[2] = fmaf(w, f1.x, acc[2]);
        acc[3] = fmaf(w, f1.y, acc[3]);
        acc[4] = fmaf(w, f2.x, acc[4]);
        acc[5] = fmaf(w, f2.y, acc[5]);
        acc[6] = fmaf(w, f3.x, acc[6]);
        acc[7] = fmaf(w, f3.y, acc[7]);
    }
    float inv = 1.f / ssum;
    int col = lane * 8;
    float o[8];
    #pragma unroll
    for (int q = 0; q < 8; q++) {
        float x = acc[q] * inv + b1[col + q];
        o[q] = (x > 0.f) ? x : (__expf(x) - 1.0f);  // elu (MUFU fast path)
    }
    __half2* dst = reinterpret_cast<__half2*>(&g_h16[(size_t)node * 256 + col]);
    dst[0] = __floats2half2_rn(o[0], o[1]);
    dst[1] = __floats2half2_rn(o[2], o[3]);
    dst[2] = __floats2half2_rn(o[4], o[5]);
    dst[3] = __floats2half2_rn(o[6], o[7]);
}

// ---------------- layer2 aggregation ---------------------------------------
__global__ void agg2_kernel(const float* __restrict__ b2,
                            float* __restrict__ out, int n) {
    int node = blockIdx.x * 8 + (threadIdx.x >> 5);
    if (node >= n) return;
    int lane = threadIdx.x & 31;
    int beg = g_offs[node], end = g_offs[node + 1];
    float adn = g_ald2[node];
    float m = -1e30f, ssum = 0.f, ax = 0.f, ay = 0.f;
    for (int j = beg; j < end; j++) {
        int s = g_ssrc[j];
        float a = g_als2[s] + adn;
        a = (a > 0.f) ? a : 0.2f * a;
        if (a > m) {
            float sc = __expf(m - a);
            ax *= sc; ay *= sc; ssum *= sc; m = a;
        }
        float w = __expf(a - m);
        ssum += w;
        float2 v = __half22float2(*reinterpret_cast<const __half2*>(
            &g_xp2h[(size_t)s * 64 + lane * 2]));
        ax = fmaf(w, v.x, ax);
        ay = fmaf(w, v.y, ay);
    }
    float inv = 1.f / ssum;
    int col = lane * 2;
    out[(size_t)node * 64 + col] =
        ax * inv + b2[col] + g_skip[(size_t)node * 64 + col];
    out[(size_t)node * 64 + col + 1] =
        ay * inv + b2[col + 1] + g_skip[(size_t)node * 64 + col + 1];
}

// ---------------- launch (three streams, event fork/join) -------------------
extern "C" void kernel_launch(void* const* d_in, const int* in_sizes, int n_in,
                              void* d_out, int out_size) {
    const float* x_clean  = (const float*)d_in[0];
    const float* x_noised = (const float*)d_in[1];
    const int*   esrc     = (const int*)d_in[2];
    const int*   edst     = (const int*)d_in[3];
    const float* W1  = (const float*)d_in[4];
    const float* as1 = (const float*)d_in[5];
    const float* ad1 = (const float*)d_in[6];
    const float* b1  = (const float*)d_in[7];
    const float* W2  = (const float*)d_in[8];
    const float* as2 = (const float*)d_in[9];
    const float* ad2 = (const float*)d_in[10];
    const float* b2  = (const float*)d_in[11];
    float* out = (float*)d_out;

    int N = in_sizes[0] / 256;  // 50000
    int E = in_sizes[2];        // 800000

    static cudaStream_t s1 = nullptr, s2 = nullptr;
    static cudaEvent_t evRoot, evCvtA, evCsr, evSkip;
    if (s1 == nullptr) {
        cudaStreamCreateWithFlags(&s1, cudaStreamNonBlocking);
        cudaStreamCreateWithFlags(&s2, cudaStreamNonBlocking);
        cudaEventCreateWithFlags(&evRoot, cudaEventDisableTiming);
        cudaEventCreateWithFlags(&evCvtA, cudaEventDisableTiming);
        cudaEventCreateWithFlags(&evCsr,  cudaEventDisableTiming);
        cudaEventCreateWithFlags(&evSkip, cudaEventDisableTiming);
        const int SMBi = (2 * 128 * 72 + 2 * 128 * 72) * 2;
        cudaFuncSetAttribute(gemm_f16<0, true>,  cudaFuncAttributeMaxDynamicSharedMemorySize, SMBi);
        cudaFuncSetAttribute(gemm_f16<1, true>,  cudaFuncAttributeMaxDynamicSharedMemorySize, SMBi);
        cudaFuncSetAttribute(gemm_f16<2, false>, cudaFuncAttributeMaxDynamicSharedMemorySize, SMBi);
    }
    const int SMB = (2 * 128 * 72 + 2 * 128 * 72) * 2;  // 73728 B

    int nb = (N + 255) / 256;       // 196
    int mtiles = (N + 127) / 128;   // 391

    // fork s1, s2 from capture stream
    cudaEventRecord(evRoot, 0);
    cudaStreamWaitEvent(s1, evRoot, 0);
    cudaStreamWaitEvent(s2, evRoot, 0);

    // s0: xa16+weights, then xp1 GEMM (y=3 incl. aug logits1)
    cvt_a_kernel<<<(NN * 256 / 4 + 255) / 256, 256>>>(
        x_noised, W1, W2, as1, ad1, as2, ad2);                                   // 1
    cudaEventRecord(evCvtA, 0);
    gemm_f16<0, true><<<dim3(mtiles, 3), 256, SMB>>>(0, 0, nullptr, 1, N, 256, 0); // 2: xp1+logits1

    // s2: xc16 -> hs -> skip
    cvt_c_kernel<<<(NN * 256 / 4 + 255) / 256, 256, 0, s2>>>(x_clean);           // 3
    cudaStreamWaitEvent(s2, evCvtA, 0);
    gemm_f16<1, true><<<dim3(mtiles, 2), 256, SMB, s2>>>(1, 0, b1, 2, N, 256, -1);  // 4: hs
    gemm_f16<2, false><<<dim3(mtiles, 1), 256, SMB, s2>>>(2, 1, b2, 3, N, 64, -1);  // 5: skip
    cudaEventRecord(evSkip, s2);

    // s1: CSR build chain (fully independent)
    init_deg_kernel<<<nb, 256, 0, s1>>>(N);                                      // 6
    count_kernel<<<(E + 255) / 256, 256, 0, s1>>>(edst, E);                      // 7
    scan_local_kernel<<<nb, 256, 0, s1>>>(N);                                    // 8
    scan_bsum_kernel<<<1, 256, 0, s1>>>(nb, N);                                  // 9
    scan_add_place_kernel<<<nb, 256, 0, s1>>>(N);                                // 10
    scatter_kernel<<<(E + 255) / 256, 256, 0, s1>>>(esrc, edst, E);              // 11
    cudaEventRecord(evCsr, s1);

    // s0: agg1 (needs xp1 + CSR), then layer 2
    cudaStreamWaitEvent(0, evCsr, 0);
    agg1_kernel<<<(N + 7) / 8, 256>>>(b1, N);                                    // 12
    gemm_f16<0, true><<<dim3(mtiles, 1), 256, SMB>>>(3, 1, nullptr, 4, N, 64, 1);   // 13: xp2+logits2
    cudaStreamWaitEvent(0, evSkip, 0);
    agg2_kernel<<<(N + 7) / 8, 256>>>(b2, out, N);                               // 14
}